// round 1
// baseline (speedup 1.0000x reference)
#include <cuda_runtime.h>

// Problem shape (fixed by the dataset): B=2, H=16, S=2048, D=64, fp32.
// Output buffer = [context (B*H*S*D floats) | weights (B*H*S*S floats)].

#define SDIM    2048
#define DDIM    64
#define BHN     32          // B*H
#define TQ      16          // queries per block
#define CK      256         // keys per chunk
#define NCH     (SDIM/CK)   // 8 chunks
#define KSTR    68          // padded row stride (floats) for K/V in smem -> conflict-free float4
#define THREADS 256

// smem layout (floats):
//   Qs  [TQ*DDIM]            = 1024
//   KVs [CK*KSTR]            = 17408   (K chunk / V chunk / ctx-partial scratch)
//   Sc  [TQ*SDIM]            = 32768   (scores -> exp weights)
//   red [128]                (warp maxes, row max, inv sums)
#define SMEM_FLOATS (1024 + 17408 + TQ*SDIM + 128)

__global__ __launch_bounds__(THREADS, 1)
void attn_fused_kernel(const float* __restrict__ Q, const float* __restrict__ K,
                       const float* __restrict__ V, const int* __restrict__ M,
                       float* __restrict__ ctx, float* __restrict__ wout)
{
    extern __shared__ float sm[];
    float* Qs  = sm;
    float* KVs = sm + 1024;
    float* Sc  = sm + 1024 + 17408;
    float* red = Sc + TQ * SDIM;

    const int t    = threadIdx.x;
    const int w    = t >> 5;
    const int lane = t & 31;
    const int bh   = blockIdx.y;
    const int q0   = blockIdx.x * TQ;

    const float* Qb = Q + ((size_t)bh * SDIM + q0) * DDIM;
    const float* Kb = K + (size_t)bh * SDIM * DDIM;
    const float* Vb = V + (size_t)bh * SDIM * DDIM;
    const int*   Mb = M + ((size_t)bh * SDIM + q0) * SDIM;
    float* Cb = ctx  + ((size_t)bh * SDIM + q0) * DDIM;
    float* Wb = wout + ((size_t)bh * SDIM + q0) * SDIM;

    // ---- load Q tile (16x64 contiguous floats = 256 float4) ----
    ((float4*)Qs)[t] = ((const float4*)Qb)[t];

    // ---- Pass A: masked scaled scores into Sc, track row max ----
    // warp w handles q rows [qbase, qbase+8), k slice kslice (2 k per thread per chunk)
    const int qbase  = (w & 1) * 8;
    const int kslice = w >> 1;
    const int k0 = lane + 32 * (kslice * 2);
    const int k1 = lane + 32 * (kslice * 2 + 1);

    float mxl[8];
#pragma unroll
    for (int r = 0; r < 8; r++) mxl[r] = -3.4e38f;

    for (int c = 0; c < NCH; c++) {
        __syncthreads();
        // load K chunk (256 x 64) into KVs with padded stride
#pragma unroll
        for (int i = t; i < CK * 16; i += THREADS) {
            int row = i >> 4, c4 = i & 15;
            float4 v = ((const float4*)(Kb + (size_t)(c * CK + row) * DDIM))[c4];
            *(float4*)(KVs + row * KSTR + c4 * 4) = v;
        }
        __syncthreads();

        float acc[8][2];
#pragma unroll
        for (int r = 0; r < 8; r++) { acc[r][0] = 0.f; acc[r][1] = 0.f; }

#pragma unroll
        for (int d4 = 0; d4 < 16; d4++) {
            float4 kv0 = *(const float4*)(KVs + k0 * KSTR + d4 * 4);
            float4 kv1 = *(const float4*)(KVs + k1 * KSTR + d4 * 4);
#pragma unroll
            for (int r = 0; r < 8; r++) {
                float4 qv = ((const float4*)(Qs + (qbase + r) * DDIM))[d4];
                acc[r][0] += qv.x*kv0.x + qv.y*kv0.y + qv.z*kv0.z + qv.w*kv0.w;
                acc[r][1] += qv.x*kv1.x + qv.y*kv1.y + qv.z*kv1.z + qv.w*kv1.w;
            }
        }

#pragma unroll
        for (int r = 0; r < 8; r++) {
            int q = qbase + r;
#pragma unroll
            for (int jj = 0; jj < 2; jj++) {
                int kk = jj ? k1 : k0;
                int kg = c * CK + kk;
                int m  = Mb[(size_t)q * SDIM + kg];
                float s = m ? -1e9f : acc[r][jj] * 0.125f;  // SCALE = 1/sqrt(64)
                Sc[q * SDIM + kg] = s;
                mxl[r] = fmaxf(mxl[r], s);
            }
        }
    }

    // ---- row max reduction ----
#pragma unroll
    for (int r = 0; r < 8; r++) {
        float v = mxl[r];
#pragma unroll
        for (int o = 16; o > 0; o >>= 1)
            v = fmaxf(v, __shfl_xor_sync(0xffffffffu, v, o));
        mxl[r] = v;
    }
    __syncthreads();
    if (lane == 0) {
#pragma unroll
        for (int r = 0; r < 8; r++) red[w * 8 + r] = mxl[r];
    }
    __syncthreads();
    if (t < 16) {
        int p = t >> 3, r = t & 7;
        float m = red[p * 8 + r];
        m = fmaxf(m, red[(p + 2) * 8 + r]);
        m = fmaxf(m, red[(p + 4) * 8 + r]);
        m = fmaxf(m, red[(p + 6) * 8 + r]);
        red[64 + t] = m;   // row max
    }
    __syncthreads();

    // ---- exp in-place + row sums ----
    {
        const int tq = t >> 4, tk = t & 15;
        const float m = red[64 + tq];
        float ssum = 0.f;
        float4* Sc4 = (float4*)(Sc + tq * SDIM);
#pragma unroll 8
        for (int j = 0; j < 32; j++) {
            int i4 = tk + 16 * j;
            float4 s = Sc4[i4];
            s.x = __expf(s.x - m); s.y = __expf(s.y - m);
            s.z = __expf(s.z - m); s.w = __expf(s.w - m);
            Sc4[i4] = s;
            ssum += (s.x + s.y) + (s.z + s.w);
        }
#pragma unroll
        for (int o = 8; o > 0; o >>= 1)
            ssum += __shfl_xor_sync(0xffffffffu, ssum, o);
        if (tk == 0) red[80 + tq] = 1.0f / ssum;  // inv sum
    }
    __syncthreads();

    // ---- Pass B: context = expW @ V (4 k-slices, partials reduced via smem) ----
    const int s2  = t >> 6;        // k slice 0..3
    const int t64 = t & 63;
    const int qg  = t64 >> 4;      // q group 0..3 (4 rows each)
    const int dg  = t64 & 15;      // d float4 column 0..15

    float4 cacc[4];
#pragma unroll
    for (int rr = 0; rr < 4; rr++) cacc[rr] = make_float4(0.f, 0.f, 0.f, 0.f);

    for (int c = 0; c < NCH; c++) {
        __syncthreads();
#pragma unroll
        for (int i = t; i < CK * 16; i += THREADS) {
            int row = i >> 4, c4 = i & 15;
            float4 v = ((const float4*)(Vb + (size_t)(c * CK + row) * DDIM))[c4];
            *(float4*)(KVs + row * KSTR + c4 * 4) = v;
        }
        __syncthreads();

#pragma unroll
        for (int kk4 = 0; kk4 < 16; kk4++) {
            int krow = s2 * 64 + kk4 * 4;
            float4 v0 = *(const float4*)(KVs + (krow + 0) * KSTR + dg * 4);
            float4 v1 = *(const float4*)(KVs + (krow + 1) * KSTR + dg * 4);
            float4 v2 = *(const float4*)(KVs + (krow + 2) * KSTR + dg * 4);
            float4 v3 = *(const float4*)(KVs + (krow + 3) * KSTR + dg * 4);
#pragma unroll
            for (int rr = 0; rr < 4; rr++) {
                int q = qg * 4 + rr;
                float4 wv = ((const float4*)(Sc + q * SDIM))[c * 64 + s2 * 16 + kk4];
                cacc[rr].x += wv.x*v0.x + wv.y*v1.x + wv.z*v2.x + wv.w*v3.x;
                cacc[rr].y += wv.x*v0.y + wv.y*v1.y + wv.z*v2.y + wv.w*v3.y;
                cacc[rr].z += wv.x*v0.z + wv.y*v1.z + wv.z*v2.z + wv.w*v3.z;
                cacc[rr].w += wv.x*v0.w + wv.y*v1.w + wv.z*v2.w + wv.w*v3.w;
            }
        }
    }
    __syncthreads();
    // stash slice partials in KVs (V no longer needed): partial[s2][q][d]
#pragma unroll
    for (int rr = 0; rr < 4; rr++) {
        int q = qg * 4 + rr;
        ((float4*)KVs)[(s2 * 16 + q) * 16 + dg] = cacc[rr];
    }
    __syncthreads();

    // ---- final context: sum 4 slices, scale by inv sum, write ----
#pragma unroll
    for (int j = 0; j < 4; j++) {
        int o = t + 256 * j;           // 0..1023
        int q = o >> 6, d = o & 63;
        float v = KVs[q * 64 + d] + KVs[1024 + q * 64 + d]
                + KVs[2048 + q * 64 + d] + KVs[3072 + q * 64 + d];
        Cb[o] = v * red[80 + q];
    }

    // ---- Pass C: normalized weights to gmem ----
    {
        const int tq = t >> 4, tk = t & 15;
        const float is = red[80 + tq];
        const float4* Sc4 = (const float4*)(Sc + tq * SDIM);
        float4* W4 = (float4*)(Wb + (size_t)tq * SDIM);
#pragma unroll 8
        for (int j = 0; j < 32; j++) {
            int i4 = tk + 16 * j;
            float4 s = Sc4[i4];
            s.x *= is; s.y *= is; s.z *= is; s.w *= is;
            W4[i4] = s;
        }
    }
}

extern "C" void kernel_launch(void* const* d_in, const int* in_sizes, int n_in,
                              void* d_out, int out_size)
{
    const float* Q = (const float*)d_in[0];
    const float* K = (const float*)d_in[1];
    const float* V = (const float*)d_in[2];
    const int*   M = (const int*)d_in[3];

    float* ctx  = (float*)d_out;                                  // B*H*S*D
    float* wout = (float*)d_out + (size_t)BHN * SDIM * DDIM;      // B*H*S*S

    const size_t smem = (size_t)SMEM_FLOATS * sizeof(float);      // ~205 KB
    cudaFuncSetAttribute(attn_fused_kernel,
                         cudaFuncAttributeMaxDynamicSharedMemorySize, (int)smem);

    dim3 grid(SDIM / TQ, BHN);   // x-fastest -> consecutive blocks share a head's K/V in L2
    attn_fused_kernel<<<grid, THREADS, smem>>>(Q, K, V, M, ctx, wout);
}

// round 2
// speedup vs baseline: 1.3424x; 1.3424x over previous
#include <cuda_runtime.h>
#include <cstdint>

// B=2, H=16, S=2048, D=64 fp32 attention; out = [context | weights].
// tf32 mma.sync for both GEMMs; fp32 softmax.

#define SDIM    2048
#define DDIM    64
#define BHN     32
#define TQ      16          // queries per CTA
#define CK      256         // keys per smem chunk
#define NCH     (SDIM/CK)
#define KSTR    68          // K/V smem row stride (floats) -> bank-bijective frags
#define QSTR    68
#define SSTR    2052        // score smem row stride -> bank-bijective A frags
#define THREADS 256
#define SCALE   0.125f

#define SMEM_FLOATS (TQ*QSTR + CK*KSTR + TQ*SSTR + 64)

__device__ __forceinline__ uint32_t f2tf(float f) {
    uint32_t r;
    asm("cvt.rna.tf32.f32 %0, %1;" : "=r"(r) : "f"(f));
    return r;
}

__device__ __forceinline__ void mma_tf32(float c[4],
    uint32_t a0, uint32_t a1, uint32_t a2, uint32_t a3,
    uint32_t b0, uint32_t b1)
{
    asm volatile(
        "mma.sync.aligned.m16n8k8.row.col.f32.tf32.tf32.f32 "
        "{%0,%1,%2,%3}, {%4,%5,%6,%7}, {%8,%9}, {%0,%1,%2,%3};"
        : "+f"(c[0]), "+f"(c[1]), "+f"(c[2]), "+f"(c[3])
        : "r"(a0), "r"(a1), "r"(a2), "r"(a3), "r"(b0), "r"(b1));
}

__global__ __launch_bounds__(THREADS, 1)
void attn_tf32_kernel(const float* __restrict__ Q, const float* __restrict__ K,
                      const float* __restrict__ V, const int* __restrict__ M,
                      float* __restrict__ ctx, float* __restrict__ wout)
{
    extern __shared__ float sm[];
    float* Qs  = sm;                       // 16 x 68
    float* KVs = Qs + TQ * QSTR;           // 256 x 68 (K chunk, then V chunk)
    float* Sc  = KVs + CK * KSTR;          // 16 x 2052 (scores -> exp weights)
    float* red = Sc + TQ * SSTR;           // [0..15] row max, [32..47] inv sum

    const int t    = threadIdx.x;
    const int w    = t >> 5;
    const int lane = t & 31;
    const int grp  = lane >> 2;            // 0..7
    const int tig  = lane & 3;             // 0..3
    const int bh   = blockIdx.y;
    const int q0   = blockIdx.x * TQ;

    const float* Qb = Q + ((size_t)bh * SDIM + q0) * DDIM;
    const float* Kb = K + (size_t)bh * SDIM * DDIM;
    const float* Vb = V + (size_t)bh * SDIM * DDIM;
    const int*   Mb = M + ((size_t)bh * SDIM + q0) * SDIM;
    float* Cb = ctx  + ((size_t)bh * SDIM + q0) * DDIM;
    float* Wb = wout + ((size_t)bh * SDIM + q0) * SDIM;

    // ---- load Q tile into padded smem ----
    {
        int row = t >> 4, c4 = t & 15;
        float4 v = ((const float4*)(Qb + (size_t)row * DDIM))[c4];
        *(float4*)(Qs + row * QSTR + c4 * 4) = v;
    }
    __syncthreads();

    // ---- A fragments for Q (16x64): 8 k-steps x 4 regs, resident all of Pass A ----
    uint32_t aq[8][4];
#pragma unroll
    for (int ks = 0; ks < 8; ks++) {
        const float* qr0 = Qs + grp * QSTR + ks * 8;
        const float* qr1 = Qs + (grp + 8) * QSTR + ks * 8;
        aq[ks][0] = f2tf(qr0[tig]);
        aq[ks][1] = f2tf(qr1[tig]);
        aq[ks][2] = f2tf(qr0[tig + 4]);
        aq[ks][3] = f2tf(qr1[tig + 4]);
    }

    // ---- Pass A: scores = scale * Q K^T into Sc (no mask yet) ----
    for (int c = 0; c < NCH; c++) {
        __syncthreads();
#pragma unroll
        for (int i = t; i < CK * 16; i += THREADS) {
            int row = i >> 4, c4 = i & 15;
            float4 v = ((const float4*)(Kb + (size_t)(c * CK + row) * DDIM))[c4];
            *(float4*)(KVs + row * KSTR + c4 * 4) = v;
        }
        __syncthreads();

#pragma unroll
        for (int nt = 0; nt < 4; nt++) {
            float acc[4] = {0.f, 0.f, 0.f, 0.f};
            const int keyrow = w * 32 + nt * 8 + grp;   // key within chunk
            const float* kr = KVs + keyrow * KSTR;
#pragma unroll
            for (int ks = 0; ks < 8; ks++) {
                uint32_t b0 = f2tf(kr[ks * 8 + tig]);
                uint32_t b1 = f2tf(kr[ks * 8 + tig + 4]);
                mma_tf32(acc, aq[ks][0], aq[ks][1], aq[ks][2], aq[ks][3], b0, b1);
            }
            int col0 = c * CK + w * 32 + nt * 8 + tig * 2;
            *(float2*)(Sc + grp * SSTR + col0) =
                make_float2(acc[0] * SCALE, acc[1] * SCALE);
            *(float2*)(Sc + (grp + 8) * SSTR + col0) =
                make_float2(acc[2] * SCALE, acc[3] * SCALE);
        }
    }
    __syncthreads();

    // ---- mask apply (coalesced int4 gmem read) + row max ----
    {
        const int row = t >> 4, tk = t & 15;
        const int4* M4 = (const int4*)(Mb + (size_t)row * SDIM);
        float4* S4 = (float4*)(Sc + row * SSTR);
        float mx = -3.4e38f;
#pragma unroll 4
        for (int j = 0; j < 32; j++) {
            int i4 = tk + 16 * j;
            int4  m = M4[i4];
            float4 s = S4[i4];
            if (m.x) s.x = -1e9f;
            if (m.y) s.y = -1e9f;
            if (m.z) s.z = -1e9f;
            if (m.w) s.w = -1e9f;
            S4[i4] = s;
            mx = fmaxf(mx, fmaxf(fmaxf(s.x, s.y), fmaxf(s.z, s.w)));
        }
#pragma unroll
        for (int o = 8; o > 0; o >>= 1)
            mx = fmaxf(mx, __shfl_xor_sync(0xffffffffu, mx, o, 16));
        if (tk == 0) red[row] = mx;
    }
    __syncthreads();

    // ---- exp in-place + inv row sum ----
    {
        const int row = t >> 4, tk = t & 15;
        const float m = red[row];
        float4* S4 = (float4*)(Sc + row * SSTR);
        float ssum = 0.f;
#pragma unroll 4
        for (int j = 0; j < 32; j++) {
            int i4 = tk + 16 * j;
            float4 s = S4[i4];
            s.x = __expf(s.x - m); s.y = __expf(s.y - m);
            s.z = __expf(s.z - m); s.w = __expf(s.w - m);
            S4[i4] = s;
            ssum += (s.x + s.y) + (s.z + s.w);
        }
#pragma unroll
        for (int o = 8; o > 0; o >>= 1)
            ssum += __shfl_xor_sync(0xffffffffu, ssum, o, 16);
        if (tk == 0) red[32 + row] = 1.0f / ssum;
    }
    __syncthreads();

    // ---- Pass B: context = W @ V via tf32 mma; warp w owns d-cols [w*8, w*8+8) ----
    float cc[4] = {0.f, 0.f, 0.f, 0.f};
    for (int c = 0; c < NCH; c++) {
        __syncthreads();
#pragma unroll
        for (int i = t; i < CK * 16; i += THREADS) {
            int row = i >> 4, c4 = i & 15;
            float4 v = ((const float4*)(Vb + (size_t)(c * CK + row) * DDIM))[c4];
            *(float4*)(KVs + row * KSTR + c4 * 4) = v;
        }
        __syncthreads();

#pragma unroll 4
        for (int ks = 0; ks < 32; ks++) {
            const float* ar = Sc + grp * SSTR + c * CK + ks * 8;
            uint32_t a0 = f2tf(ar[tig]);
            uint32_t a1 = f2tf(ar[8 * SSTR + tig]);
            uint32_t a2 = f2tf(ar[tig + 4]);
            uint32_t a3 = f2tf(ar[8 * SSTR + tig + 4]);
            const float* vr = KVs + (ks * 8 + tig) * KSTR + w * 8 + grp;
            uint32_t b0 = f2tf(vr[0]);
            uint32_t b1 = f2tf(vr[4 * KSTR]);
            mma_tf32(cc, a0, a1, a2, a3, b0, b1);
        }
    }
    {
        const float is0 = red[32 + grp];
        const float is1 = red[32 + grp + 8];
        int d0 = w * 8 + tig * 2;
        *(float2*)(Cb + (size_t)grp * DDIM + d0) =
            make_float2(cc[0] * is0, cc[1] * is0);
        *(float2*)(Cb + (size_t)(grp + 8) * DDIM + d0) =
            make_float2(cc[2] * is1, cc[3] * is1);
    }

    // ---- normalize + stream weights to gmem ----
    {
        const int row = t >> 4, tk = t & 15;
        const float is = red[32 + row];
        const float4* S4 = (const float4*)(Sc + row * SSTR);
        float4* W4 = (float4*)(Wb + (size_t)row * SDIM);
#pragma unroll 4
        for (int j = 0; j < 32; j++) {
            int i4 = tk + 16 * j;
            float4 s = S4[i4];
            s.x *= is; s.y *= is; s.z *= is; s.w *= is;
            W4[i4] = s;
        }
    }
}

extern "C" void kernel_launch(void* const* d_in, const int* in_sizes, int n_in,
                              void* d_out, int out_size)
{
    const float* Q = (const float*)d_in[0];
    const float* K = (const float*)d_in[1];
    const float* V = (const float*)d_in[2];
    const int*   M = (const int*)d_in[3];

    float* ctx  = (float*)d_out;
    float* wout = (float*)d_out + (size_t)BHN * SDIM * DDIM;

    const size_t smem = (size_t)SMEM_FLOATS * sizeof(float);   // ~206 KB
    cudaFuncSetAttribute(attn_tf32_kernel,
                         cudaFuncAttributeMaxDynamicSharedMemorySize, (int)smem);

    dim3 grid(SDIM / TQ, BHN);
    attn_tf32_kernel<<<grid, THREADS, smem>>>(Q, K, V, M, ctx, wout);
}

// round 3
// speedup vs baseline: 1.7014x; 1.2674x over previous
#include <cuda_runtime.h>
#include <cstdint>

// B=2, H=16, S=2048, D=64 fp32 attention; out = [context | weights].
// tf32 mma for both GEMMs; warp-partitioned-k Pass B; fused mask / inline exp.

#define SDIM    2048
#define DDIM    64
#define BHN     32
#define TQ      16
#define CK      256
#define NCH     8
#define QSTR    68
#define KSTRA   68     // K chunk stride: Pass-A B-frags conflict-free
#define KSTRB   72     // V chunk stride: Pass-B B-frags conflict-free
#define SSTR    2052
#define THREADS 512
#define SCALE   0.125f

// floats: Qs 1088 | KV 18432 (=16*1152, reused for partials) | Sc 32832 | red 320
#define SMEM_FLOATS (1088 + 18432 + 32832 + 320)

__device__ __forceinline__ uint32_t f2tf(float f) {
    uint32_t r;
    asm("cvt.rna.tf32.f32 %0, %1;" : "=r"(r) : "f"(f));
    return r;
}

__device__ __forceinline__ void mma_tf32(float c[4],
    uint32_t a0, uint32_t a1, uint32_t a2, uint32_t a3,
    uint32_t b0, uint32_t b1)
{
    asm volatile(
        "mma.sync.aligned.m16n8k8.row.col.f32.tf32.tf32.f32 "
        "{%0,%1,%2,%3}, {%4,%5,%6,%7}, {%8,%9}, {%0,%1,%2,%3};"
        : "+f"(c[0]), "+f"(c[1]), "+f"(c[2]), "+f"(c[3])
        : "r"(a0), "r"(a1), "r"(a2), "r"(a3), "r"(b0), "r"(b1));
}

__global__ __launch_bounds__(THREADS, 1)
void attn_tf32_v3(const float* __restrict__ Q, const float* __restrict__ K,
                  const float* __restrict__ V, const int* __restrict__ M,
                  float* __restrict__ ctx, float* __restrict__ wout)
{
    extern __shared__ float sm[];
    float* Qs   = sm;                         // 16 x 68
    float* KVs  = sm + 1088;                  // 256 x 72 max (K@68 / V@72 / partials)
    float* Sc   = KVs + 18432;                // 16 x 2052 raw masked scores
    float* redw = Sc + TQ * SSTR;             // 256: per-warp row reductions
    float* rmax = redw + 256;                 // 16
    float* rinv = rmax + 16;                  // 16

    const int t    = threadIdx.x;
    const int w    = t >> 5;                  // 0..15
    const int lane = t & 31;
    const int grp  = lane >> 2;               // 0..7
    const int tig  = lane & 3;                // 0..3
    const int bh   = blockIdx.y;
    const int q0   = blockIdx.x * TQ;

    const float* Qb = Q + ((size_t)bh * SDIM + q0) * DDIM;
    const float* Kb = K + (size_t)bh * SDIM * DDIM;
    const float* Vb = V + (size_t)bh * SDIM * DDIM;
    const int*   Mb = M + ((size_t)bh * SDIM + q0) * SDIM;
    float* Cb = ctx  + ((size_t)bh * SDIM + q0) * DDIM;
    float* Wb = wout + ((size_t)bh * SDIM + q0) * SDIM;

    // ---- stage Q tile ----
    if (t < 256) {
        int row = t >> 4, c4 = t & 15;
        float4 v = ((const float4*)(Qb + (size_t)row * DDIM))[c4];
        *(float4*)(Qs + row * QSTR + c4 * 4) = v;
    }

    // ---- prefetch K chunk 0 ----
    float4 pf[8];
#pragma unroll
    for (int j = 0; j < 8; j++) {
        int i = t + THREADS * j, row = i >> 4, c4 = i & 15;
        pf[j] = ((const float4*)(Kb + (size_t)row * DDIM))[c4];
    }
    __syncthreads();

    // ---- Q A-fragments (resident through Pass A) ----
    uint32_t aq[8][4];
#pragma unroll
    for (int ks = 0; ks < 8; ks++) {
        const float* qr0 = Qs + grp * QSTR + ks * 8;
        const float* qr1 = Qs + (grp + 8) * QSTR + ks * 8;
        aq[ks][0] = f2tf(qr0[tig]);
        aq[ks][1] = f2tf(qr1[tig]);
        aq[ks][2] = f2tf(qr0[tig + 4]);
        aq[ks][3] = f2tf(qr1[tig + 4]);
    }

    // ---- Pass A: masked scaled scores -> Sc; per-thread row max ----
    float mx0 = -3.4e38f, mx1 = -3.4e38f;
    for (int c = 0; c < NCH; c++) {
#pragma unroll
        for (int j = 0; j < 8; j++) {
            int i = t + THREADS * j, row = i >> 4, c4 = i & 15;
            *(float4*)(KVs + row * KSTRA + c4 * 4) = pf[j];
        }
        if (c + 1 < NCH) {
#pragma unroll
            for (int j = 0; j < 8; j++) {
                int i = t + THREADS * j, row = i >> 4, c4 = i & 15;
                pf[j] = ((const float4*)(Kb + (size_t)((c + 1) * CK + row) * DDIM))[c4];
            }
        }
        __syncthreads();

#pragma unroll
        for (int nt = 0; nt < 2; nt++) {
            float acc[4] = {0.f, 0.f, 0.f, 0.f};
            const float* kr = KVs + (w * 16 + nt * 8 + grp) * KSTRA;
#pragma unroll
            for (int ks = 0; ks < 8; ks++) {
                uint32_t b0 = f2tf(kr[ks * 8 + tig]);
                uint32_t b1 = f2tf(kr[ks * 8 + tig + 4]);
                mma_tf32(acc, aq[ks][0], aq[ks][1], aq[ks][2], aq[ks][3], b0, b1);
            }
            int col0 = c * CK + w * 16 + nt * 8 + tig * 2;
            int2 m0 = *(const int2*)(Mb + (size_t)grp * SDIM + col0);
            int2 m1 = *(const int2*)(Mb + (size_t)(grp + 8) * SDIM + col0);
            float2 s0 = make_float2(m0.x ? -1e9f : acc[0] * SCALE,
                                    m0.y ? -1e9f : acc[1] * SCALE);
            float2 s1 = make_float2(m1.x ? -1e9f : acc[2] * SCALE,
                                    m1.y ? -1e9f : acc[3] * SCALE);
            *(float2*)(Sc + grp * SSTR + col0)       = s0;
            *(float2*)(Sc + (grp + 8) * SSTR + col0) = s1;
            mx0 = fmaxf(mx0, fmaxf(s0.x, s0.y));
            mx1 = fmaxf(mx1, fmaxf(s1.x, s1.y));
        }
        __syncthreads();
    }

    // ---- prefetch V chunk 0 while reducing max ----
#pragma unroll
    for (int j = 0; j < 8; j++) {
        int i = t + THREADS * j, row = i >> 4, c4 = i & 15;
        pf[j] = ((const float4*)(Vb + (size_t)row * DDIM))[c4];
    }

    // ---- row max: reduce over tig, then over 16 warps ----
    mx0 = fmaxf(mx0, __shfl_xor_sync(0xffffffffu, mx0, 1));
    mx0 = fmaxf(mx0, __shfl_xor_sync(0xffffffffu, mx0, 2));
    mx1 = fmaxf(mx1, __shfl_xor_sync(0xffffffffu, mx1, 1));
    mx1 = fmaxf(mx1, __shfl_xor_sync(0xffffffffu, mx1, 2));
    if (tig == 0) {
        redw[w * 16 + grp]     = mx0;
        redw[w * 16 + grp + 8] = mx1;
    }
    __syncthreads();
    if (t < 256) {
        int row = t >> 4, j = t & 15;
        float v = redw[j * 16 + row];
#pragma unroll
        for (int o = 8; o > 0; o >>= 1)
            v = fmaxf(v, __shfl_xor_sync(0xffffffffu, v, o));
        if (j == 0) rmax[row] = v;
    }
    __syncthreads();

    // ---- Pass B: warp-partitioned-k; exp inline; per-warp context partial ----
    const float m0 = rmax[grp], m1 = rmax[grp + 8];
    float cc[8][4];
#pragma unroll
    for (int nt = 0; nt < 8; nt++)
#pragma unroll
        for (int r = 0; r < 4; r++) cc[nt][r] = 0.f;
    float sum0 = 0.f, sum1 = 0.f;

    for (int c = 0; c < NCH; c++) {
#pragma unroll
        for (int j = 0; j < 8; j++) {
            int i = t + THREADS * j, row = i >> 4, c4 = i & 15;
            *(float4*)(KVs + row * KSTRB + c4 * 4) = pf[j];
        }
        if (c + 1 < NCH) {
#pragma unroll
            for (int j = 0; j < 8; j++) {
                int i = t + THREADS * j, row = i >> 4, c4 = i & 15;
                pf[j] = ((const float4*)(Vb + (size_t)((c + 1) * CK + row) * DDIM))[c4];
            }
        }
        __syncthreads();

#pragma unroll
        for (int ks2 = 0; ks2 < 2; ks2++) {
            const float* ar = Sc + c * CK + w * 16 + ks2 * 8;
            float e0 = __expf(ar[grp * SSTR + tig]           - m0);
            float e1 = __expf(ar[(grp + 8) * SSTR + tig]     - m1);
            float e2 = __expf(ar[grp * SSTR + tig + 4]       - m0);
            float e3 = __expf(ar[(grp + 8) * SSTR + tig + 4] - m1);
            sum0 += e0 + e2;
            sum1 += e1 + e3;
            uint32_t a0 = f2tf(e0), a1 = f2tf(e1), a2 = f2tf(e2), a3 = f2tf(e3);
            const float* vr = KVs + (w * 16 + ks2 * 8 + tig) * KSTRB;
#pragma unroll
            for (int nt = 0; nt < 8; nt++) {
                uint32_t b0 = f2tf(vr[nt * 8 + grp]);
                uint32_t b1 = f2tf(vr[4 * KSTRB + nt * 8 + grp]);
                mma_tf32(cc[nt], a0, a1, a2, a3, b0, b1);
            }
        }
        __syncthreads();
    }

    // ---- row sum: reduce over tig, then over warps -> rinv ----
    sum0 += __shfl_xor_sync(0xffffffffu, sum0, 1);
    sum0 += __shfl_xor_sync(0xffffffffu, sum0, 2);
    sum1 += __shfl_xor_sync(0xffffffffu, sum1, 1);
    sum1 += __shfl_xor_sync(0xffffffffu, sum1, 2);
    if (tig == 0) {
        redw[w * 16 + grp]     = sum0;
        redw[w * 16 + grp + 8] = sum1;
    }
    __syncthreads();
    if (t < 256) {
        int row = t >> 4, j = t & 15;
        float v = redw[j * 16 + row];
#pragma unroll
        for (int o = 8; o > 0; o >>= 1)
            v += __shfl_xor_sync(0xffffffffu, v, o);
        if (j == 0) rinv[row] = 1.0f / v;
    }
    __syncthreads();   // also: all mma done -> safe to overwrite KVs

    // ---- stage per-warp context partials; reduce; write ctx ----
#pragma unroll
    for (int nt = 0; nt < 8; nt++) {
        float* p = KVs + w * 1152 + grp * 72 + nt * 8 + tig * 2;
        *(float2*)p            = make_float2(cc[nt][0], cc[nt][1]);
        *(float2*)(p + 8 * 72) = make_float2(cc[nt][2], cc[nt][3]);
    }
    __syncthreads();
#pragma unroll
    for (int rep = 0; rep < 2; rep++) {
        int idx = t + rep * THREADS;          // 0..1023
        int row = idx >> 6, d = idx & 63;
        float s = 0.f;
#pragma unroll
        for (int w2 = 0; w2 < 16; w2++)
            s += KVs[w2 * 1152 + row * 72 + d];
        Cb[(size_t)row * DDIM + d] = s * rinv[row];
    }

    // ---- normalize weights: exp(raw - m) * rinv -> gmem ----
    {
        const int row = t >> 5, l = t & 31;
        const float m = rmax[row], ri = rinv[row];
        const float4* S4 = (const float4*)(Sc + row * SSTR);
        float4* W4 = (float4*)(Wb + (size_t)row * SDIM);
#pragma unroll 4
        for (int j = 0; j < 16; j++) {
            int i4 = l + 32 * j;
            float4 s = S4[i4];
            s.x = __expf(s.x - m) * ri;
            s.y = __expf(s.y - m) * ri;
            s.z = __expf(s.z - m) * ri;
            s.w = __expf(s.w - m) * ri;
            W4[i4] = s;
        }
    }
}

extern "C" void kernel_launch(void* const* d_in, const int* in_sizes, int n_in,
                              void* d_out, int out_size)
{
    const float* Q = (const float*)d_in[0];
    const float* K = (const float*)d_in[1];
    const float* V = (const float*)d_in[2];
    const int*   M = (const int*)d_in[3];

    float* ctx  = (float*)d_out;
    float* wout = (float*)d_out + (size_t)BHN * SDIM * DDIM;

    const size_t smem = (size_t)SMEM_FLOATS * sizeof(float);   // ~206 KB
    cudaFuncSetAttribute(attn_tf32_v3,
                         cudaFuncAttributeMaxDynamicSharedMemorySize, (int)smem);

    dim3 grid(SDIM / TQ, BHN);
    attn_tf32_v3<<<grid, THREADS, smem>>>(Q, K, V, M, ctx, wout);
}

// round 4
// speedup vs baseline: 1.7187x; 1.0102x over previous
#include <cuda_runtime.h>
#include <cstdint>

// B=2, H=16, S=2048, D=64 fp32 attention; out = [context | weights].
// Single-pass online-softmax, tf32 mma, cp.async staged K/V, register-permuted
// score->context fragments. Raw scores kept in smem only for the weights output.

#define SDIM    2048
#define DDIM    64
#define BHN     32
#define TQ      16
#define CK      128
#define NCH     16
#define QSTR    68
#define KSTR    68      // bank: 4*grp+tig distinct mod 32 -> conflict-free B frags
#define VSTR    72      // bank: 8*tig+grp distinct mod 32 -> conflict-free B frags
#define SSTR    2052
#define THREADS 512
#define SCALE   0.125f

// floats: Qs 1088 | Kbuf 8704 | Vbuf 9216 | Sc 32832 | redm 256 | reds 256 | rmax 16 | rinv 16
#define SMEM_FLOATS (1088 + 8704 + 9216 + 32832 + 256 + 256 + 32)

__device__ __forceinline__ uint32_t f2tf(float f) {
    uint32_t r;
    asm("cvt.rna.tf32.f32 %0, %1;" : "=r"(r) : "f"(f));
    return r;
}

__device__ __forceinline__ void mma_tf32(float c[4],
    uint32_t a0, uint32_t a1, uint32_t a2, uint32_t a3,
    uint32_t b0, uint32_t b1)
{
    asm volatile(
        "mma.sync.aligned.m16n8k8.row.col.f32.tf32.tf32.f32 "
        "{%0,%1,%2,%3}, {%4,%5,%6,%7}, {%8,%9}, {%0,%1,%2,%3};"
        : "+f"(c[0]), "+f"(c[1]), "+f"(c[2]), "+f"(c[3])
        : "r"(a0), "r"(a1), "r"(a2), "r"(a3), "r"(b0), "r"(b1));
}

__device__ __forceinline__ void cp16(float* dst_smem, const float* src) {
    uint32_t d = (uint32_t)__cvta_generic_to_shared(dst_smem);
    asm volatile("cp.async.cg.shared.global [%0], [%1], 16;" :: "r"(d), "l"(src));
}
#define CP_COMMIT()  asm volatile("cp.async.commit_group;" ::: "memory")
#define CP_WAIT(n)   asm volatile("cp.async.wait_group %0;" :: "n"(n) : "memory")

__global__ __launch_bounds__(THREADS, 1)
void attn_tf32_v4(const float* __restrict__ Q, const float* __restrict__ K,
                  const float* __restrict__ V, const int* __restrict__ M,
                  float* __restrict__ ctx, float* __restrict__ wout)
{
    extern __shared__ float sm[];
    float* Qs   = sm;                      // 16 x 68
    float* Kbuf = sm + 1088;               // 128 x 68
    float* Vbuf = sm + 1088 + 8704;        // 128 x 72
    float* Sc   = sm + 1088 + 8704 + 9216; // 16 x 2052 raw masked scores
    float* redm = Sc + TQ * SSTR;          // 256 per-warp row maxes
    float* reds = redm + 256;              // 256 per-warp row sums (scaled)
    float* rmax = reds + 256;              // 16
    float* rinv = rmax + 16;               // 16
    float* P    = sm + 1088;               // partials reuse K+V bufs (16 x 1088)

    const int t    = threadIdx.x;
    const int w    = t >> 5;               // 0..15
    const int lane = t & 31;
    const int grp  = lane >> 2;            // 0..7
    const int tig  = lane & 3;             // 0..3
    const bool odd = tig & 1;
    const int bh   = blockIdx.y;
    const int q0   = blockIdx.x * TQ;

    const float* Qb = Q + ((size_t)bh * SDIM + q0) * DDIM;
    const float* Kb = K + (size_t)bh * SDIM * DDIM;
    const float* Vb = V + (size_t)bh * SDIM * DDIM;
    const int*   Mb = M + ((size_t)bh * SDIM + q0) * SDIM;
    float* Cb = ctx  + ((size_t)bh * SDIM + q0) * DDIM;
    float* Wb = wout + ((size_t)bh * SDIM + q0) * SDIM;

    // ---- start K0 / V0 loads immediately ----
#pragma unroll
    for (int j = 0; j < 4; j++) {
        int i = t + THREADS * j, row = i >> 4, q = i & 15;
        cp16(Kbuf + row * KSTR + q * 4, Kb + (size_t)row * DDIM + q * 4);
    }
    CP_COMMIT();
#pragma unroll
    for (int j = 0; j < 4; j++) {
        int i = t + THREADS * j, row = i >> 4, q = i & 15;
        cp16(Vbuf + row * VSTR + q * 4, Vb + (size_t)row * DDIM + q * 4);
    }
    CP_COMMIT();

    // ---- stage Q tile ----
    if (t < 256) {
        int row = t >> 4, c4 = t & 15;
        float4 v = ((const float4*)(Qb + (size_t)row * DDIM))[c4];
        *(float4*)(Qs + row * QSTR + c4 * 4) = v;
    }
    __syncthreads();

    // ---- Q A-fragments, resident for the whole loop ----
    uint32_t aq[8][4];
#pragma unroll
    for (int ks = 0; ks < 8; ks++) {
        const float* qr0 = Qs + grp * QSTR + ks * 8;
        const float* qr1 = Qs + (grp + 8) * QSTR + ks * 8;
        aq[ks][0] = f2tf(qr0[tig]);
        aq[ks][1] = f2tf(qr1[tig]);
        aq[ks][2] = f2tf(qr0[tig + 4]);
        aq[ks][3] = f2tf(qr1[tig + 4]);
    }

    float m0 = -3.4e38f, m1 = -3.4e38f;
    float sum0 = 0.f, sum1 = 0.f;
    float cc[8][4];
#pragma unroll
    for (int nt = 0; nt < 8; nt++)
#pragma unroll
        for (int r = 0; r < 4; r++) cc[nt][r] = 0.f;

    const int base = lane & ~3;
    const int src0 = base + (tig >> 1);
    const int src2 = src0 + 2;

    // ================= unified online-softmax chunk loop =================
    for (int c = 0; c < NCH; c++) {
        CP_WAIT(1);            // K[c] resident (V[c] may still be in flight)
        __syncthreads();

        const int col0 = c * CK + w * 8 + tig * 2;
        int2 mk0 = *(const int2*)(Mb + (size_t)grp * SDIM + col0);
        int2 mk1 = *(const int2*)(Mb + (size_t)(grp + 8) * SDIM + col0);

        // ---- scores: 16q x 8k tile per warp ----
        float acc[4] = {0.f, 0.f, 0.f, 0.f};
        const float* kr = Kbuf + (w * 8 + grp) * KSTR;
#pragma unroll
        for (int ks = 0; ks < 8; ks++) {
            uint32_t b0 = f2tf(kr[ks * 8 + tig]);
            uint32_t b1 = f2tf(kr[ks * 8 + tig + 4]);
            mma_tf32(acc, aq[ks][0], aq[ks][1], aq[ks][2], aq[ks][3], b0, b1);
        }
        float s00 = mk0.x ? -1e9f : acc[0] * SCALE;
        float s01 = mk0.y ? -1e9f : acc[1] * SCALE;
        float s10 = mk1.x ? -1e9f : acc[2] * SCALE;
        float s11 = mk1.y ? -1e9f : acc[3] * SCALE;
        *(float2*)(Sc + grp * SSTR + col0)       = make_float2(s00, s01);
        *(float2*)(Sc + (grp + 8) * SSTR + col0) = make_float2(s10, s11);

        // ---- online max/sum update ----
        float cm0 = fmaxf(s00, s01), cm1 = fmaxf(s10, s11);
        cm0 = fmaxf(cm0, __shfl_xor_sync(0xffffffffu, cm0, 1));
        cm0 = fmaxf(cm0, __shfl_xor_sync(0xffffffffu, cm0, 2));
        cm1 = fmaxf(cm1, __shfl_xor_sync(0xffffffffu, cm1, 1));
        cm1 = fmaxf(cm1, __shfl_xor_sync(0xffffffffu, cm1, 2));
        float nm0 = fmaxf(m0, cm0), nm1 = fmaxf(m1, cm1);
        float f0 = __expf(m0 - nm0), f1 = __expf(m1 - nm1);
        m0 = nm0; m1 = nm1;

        float e00 = __expf(s00 - nm0), e01 = __expf(s01 - nm0);
        float e10 = __expf(s10 - nm1), e11 = __expf(s11 - nm1);
        sum0 = sum0 * f0 + (e00 + e01);
        sum1 = sum1 * f1 + (e10 + e11);

        // ---- permute accumulator layout -> A-fragment layout (regs only) ----
        float x0 = __shfl_sync(0xffffffffu, e00, src0);
        float x1 = __shfl_sync(0xffffffffu, e01, src0);
        float y0 = __shfl_sync(0xffffffffu, e00, src2);
        float y1 = __shfl_sync(0xffffffffu, e01, src2);
        float z0 = __shfl_sync(0xffffffffu, e10, src0);
        float z1 = __shfl_sync(0xffffffffu, e11, src0);
        float u0 = __shfl_sync(0xffffffffu, e10, src2);
        float u1 = __shfl_sync(0xffffffffu, e11, src2);
        uint32_t a0 = f2tf(odd ? x1 : x0);
        uint32_t a1 = f2tf(odd ? z1 : z0);
        uint32_t a2 = f2tf(odd ? y1 : y0);
        uint32_t a3 = f2tf(odd ? u1 : u0);

        // ---- rescale running context ----
#pragma unroll
        for (int nt = 0; nt < 8; nt++) {
            cc[nt][0] *= f0; cc[nt][1] *= f0;
            cc[nt][2] *= f1; cc[nt][3] *= f1;
        }

        CP_WAIT(0);            // V[c] resident
        __syncthreads();       // everyone done reading Kbuf
        if (c + 1 < NCH) {     // K[c+1] loads overlap context compute
#pragma unroll
            for (int j = 0; j < 4; j++) {
                int i = t + THREADS * j, row = i >> 4, q = i & 15;
                cp16(Kbuf + row * KSTR + q * 4,
                     Kb + (size_t)((c + 1) * CK + row) * DDIM + q * 4);
            }
            CP_COMMIT();
        }

        // ---- context: E(16x8) @ V(8x64) ----
        const float* vr = Vbuf + (w * 8 + tig) * VSTR;
#pragma unroll
        for (int nt = 0; nt < 8; nt++) {
            uint32_t b0 = f2tf(vr[nt * 8 + grp]);
            uint32_t b1 = f2tf(vr[4 * VSTR + nt * 8 + grp]);
            mma_tf32(cc[nt], a0, a1, a2, a3, b0, b1);
        }

        __syncthreads();       // everyone done reading Vbuf
        if (c + 1 < NCH) {     // V[c+1] loads overlap next score compute
#pragma unroll
            for (int j = 0; j < 4; j++) {
                int i = t + THREADS * j, row = i >> 4, q = i & 15;
                cp16(Vbuf + row * VSTR + q * 4,
                     Vb + (size_t)((c + 1) * CK + row) * DDIM + q * 4);
            }
            CP_COMMIT();
        }
    }

    // ================= cross-warp merge =================
    sum0 += __shfl_xor_sync(0xffffffffu, sum0, 1);
    sum0 += __shfl_xor_sync(0xffffffffu, sum0, 2);
    sum1 += __shfl_xor_sync(0xffffffffu, sum1, 1);
    sum1 += __shfl_xor_sync(0xffffffffu, sum1, 2);
    if (tig == 0) {
        redm[w * 16 + grp]     = m0;
        redm[w * 16 + grp + 8] = m1;
    }
    __syncthreads();
    if (t < 256) {
        int row = t >> 4, j = t & 15;
        float v = redm[j * 16 + row];
#pragma unroll
        for (int o = 8; o > 0; o >>= 1)
            v = fmaxf(v, __shfl_xor_sync(0xffffffffu, v, o));
        if (j == 0) rmax[row] = v;
    }
    __syncthreads();

    const float g0 = __expf(m0 - rmax[grp]);
    const float g1 = __expf(m1 - rmax[grp + 8]);
    if (tig == 0) {
        reds[w * 16 + grp]     = sum0 * g0;
        reds[w * 16 + grp + 8] = sum1 * g1;
    }
    // stage per-warp context partials (scaled to global max); reuse K/V smem
#pragma unroll
    for (int nt = 0; nt < 8; nt++) {
        float* p = P + w * 1088 + grp * 68 + nt * 8 + tig * 2;
        *(float2*)p            = make_float2(cc[nt][0] * g0, cc[nt][1] * g0);
        *(float2*)(p + 8 * 68) = make_float2(cc[nt][2] * g1, cc[nt][3] * g1);
    }
    __syncthreads();
    if (t < 256) {
        int row = t >> 4, j = t & 15;
        float v = reds[j * 16 + row];
#pragma unroll
        for (int o = 8; o > 0; o >>= 1)
            v += __shfl_xor_sync(0xffffffffu, v, o);
        if (j == 0) rinv[row] = 1.0f / v;
    }
    __syncthreads();

    // ---- context out ----
#pragma unroll
    for (int rep = 0; rep < 2; rep++) {
        int idx = t + rep * THREADS;        // 0..1023
        int row = idx >> 6, d = idx & 63;
        float s = 0.f;
#pragma unroll
        for (int w2 = 0; w2 < 16; w2++)
            s += P[w2 * 1088 + row * 68 + d];
        Cb[(size_t)row * DDIM + d] = s * rinv[row];
    }

    // ---- weights out: exp(raw - m) * rinv ----
    {
        const int row = t >> 5, l = t & 31;
        const float m = rmax[row], ri = rinv[row];
        const float4* S4 = (const float4*)(Sc + row * SSTR);
        float4* W4 = (float4*)(Wb + (size_t)row * SDIM);
#pragma unroll 4
        for (int j = 0; j < 16; j++) {
            int i4 = l + 32 * j;
            float4 s = S4[i4];
            s.x = __expf(s.x - m) * ri;
            s.y = __expf(s.y - m) * ri;
            s.z = __expf(s.z - m) * ri;
            s.w = __expf(s.w - m) * ri;
            W4[i4] = s;
        }
    }
}

extern "C" void kernel_launch(void* const* d_in, const int* in_sizes, int n_in,
                              void* d_out, int out_size)
{
    const float* Q = (const float*)d_in[0];
    const float* K = (const float*)d_in[1];
    const float* V = (const float*)d_in[2];
    const int*   M = (const int*)d_in[3];

    float* ctx  = (float*)d_out;
    float* wout = (float*)d_out + (size_t)BHN * SDIM * DDIM;

    const size_t smem = (size_t)SMEM_FLOATS * sizeof(float);   // ~205 KB
    cudaFuncSetAttribute(attn_tf32_v4,
                         cudaFuncAttributeMaxDynamicSharedMemorySize, (int)smem);

    dim3 grid(SDIM / TQ, BHN);
    attn_tf32_v4<<<grid, THREADS, smem>>>(Q, K, V, M, ctx, wout);
}

// round 5
// speedup vs baseline: 2.2982x; 1.3372x over previous
#include <cuda_runtime.h>
#include <cstdint>

// B=2, H=16, S=2048, D=64 fp32 attention; out = [context | weights].
// Kernel 1: flash-style online softmax, tf32 mma, raw scores streamed to the
//           gmem weights buffer, per-row max / inv-sum to __device__ scratch.
// Kernel 2: elementwise normalize of the weights buffer.

#define SDIM    2048
#define DDIM    64
#define BHN     32
#define TQ      128       // queries per CTA
#define WQ      16        // queries per warp (warp-private rows)
#define CK      64        // keys per chunk
#define NCH     32
#define KSTR    68        // conflict-free score B-frags (4*grp+tig mod 32)
#define VSTR    72        // conflict-free context B-frags (8*tig+grp mod 32)
#define STSTR   72        // stage: 8*grp+2*tig conflict-free float2 stores
#define THREADS 256
#define SCALE   0.125f

// floats: Kbuf 2*64*68 = 8704 | Vbuf 2*64*72 = 9216 | stage 8*16*72 = 9216
#define SMEM_FLOATS (8704 + 9216 + 9216)

__device__ float g_m [BHN * SDIM];
__device__ float g_ri[BHN * SDIM];

__device__ __forceinline__ uint32_t f2tf(float f) {
    uint32_t r;
    asm("cvt.rna.tf32.f32 %0, %1;" : "=r"(r) : "f"(f));
    return r;
}

__device__ __forceinline__ void mma_tf32(float c[4],
    uint32_t a0, uint32_t a1, uint32_t a2, uint32_t a3,
    uint32_t b0, uint32_t b1)
{
    asm volatile(
        "mma.sync.aligned.m16n8k8.row.col.f32.tf32.tf32.f32 "
        "{%0,%1,%2,%3}, {%4,%5,%6,%7}, {%8,%9}, {%0,%1,%2,%3};"
        : "+f"(c[0]), "+f"(c[1]), "+f"(c[2]), "+f"(c[3])
        : "r"(a0), "r"(a1), "r"(a2), "r"(a3), "r"(b0), "r"(b1));
}

__device__ __forceinline__ void cp16(float* dst_smem, const float* src) {
    uint32_t d = (uint32_t)__cvta_generic_to_shared(dst_smem);
    asm volatile("cp.async.cg.shared.global [%0], [%1], 16;" :: "r"(d), "l"(src));
}
#define CP_COMMIT()  asm volatile("cp.async.commit_group;" ::: "memory")
#define CP_WAIT0()   asm volatile("cp.async.wait_group 0;" ::: "memory")

__global__ __launch_bounds__(THREADS, 2)
void attn_pass1(const float* __restrict__ Q, const float* __restrict__ K,
                const float* __restrict__ V, const int* __restrict__ M,
                float* __restrict__ ctx, float* __restrict__ wout)
{
    extern __shared__ float sm[];
    float* Kbuf = sm;                    // [2][64 x 68]
    float* Vbuf = sm + 8704;             // [2][64 x 72]
    float* Sst  = sm + 8704 + 9216;      // [8 warps][16 x 72]

    const int t    = threadIdx.x;
    const int w    = t >> 5;             // 0..7
    const int lane = t & 31;
    const int grp  = lane >> 2;          // 0..7
    const int tig  = lane & 3;           // 0..3
    const bool odd = tig & 1;
    const int bh   = blockIdx.y;
    const int q0   = blockIdx.x * TQ;
    const int qw   = q0 + w * WQ;        // warp-private first row

    const float* Kb = K + (size_t)bh * SDIM * DDIM;
    const float* Vb = V + (size_t)bh * SDIM * DDIM;
    const float* Qw = Q + ((size_t)bh * SDIM + qw) * DDIM;
    const int*   Mw = M + ((size_t)bh * SDIM + qw) * SDIM;
    float* Cw = ctx  + ((size_t)bh * SDIM + qw) * DDIM;
    float* Ww = wout + ((size_t)bh * SDIM + qw) * SDIM;

    // ---- start chunk-0 loads ----
#pragma unroll
    for (int j = 0; j < 4; j++) {
        int i = t + THREADS * j, row = i >> 4, q = i & 15;
        cp16(Kbuf + row * KSTR + q * 4, Kb + (size_t)row * DDIM + q * 4);
        cp16(Vbuf + row * VSTR + q * 4, Vb + (size_t)row * DDIM + q * 4);
    }
    CP_COMMIT();

    // ---- Q A-fragments direct from gmem (once) ----
    uint32_t aq[8][4];
#pragma unroll
    for (int ks = 0; ks < 8; ks++) {
        aq[ks][0] = f2tf(Qw[(size_t)grp * DDIM + ks * 8 + tig]);
        aq[ks][1] = f2tf(Qw[(size_t)(grp + 8) * DDIM + ks * 8 + tig]);
        aq[ks][2] = f2tf(Qw[(size_t)grp * DDIM + ks * 8 + tig + 4]);
        aq[ks][3] = f2tf(Qw[(size_t)(grp + 8) * DDIM + ks * 8 + tig + 4]);
    }

    float m0 = -3.4e38f, m1 = -3.4e38f, sum0 = 0.f, sum1 = 0.f;
    float cc[8][4];
#pragma unroll
    for (int dn = 0; dn < 8; dn++)
#pragma unroll
        for (int r = 0; r < 4; r++) cc[dn][r] = 0.f;

    const int base = lane & ~3;
    const int src0 = base + (tig >> 1);
    const int src2 = src0 + 2;
    float* stg = Sst + w * (WQ * STSTR);

    // ================= chunk loop (one barrier per chunk) =================
    for (int c = 0; c < NCH; c++) {
        CP_WAIT0();
        __syncthreads();
        if (c + 1 < NCH) {
            float* kd = Kbuf + ((c + 1) & 1) * (64 * KSTR);
            float* vd = Vbuf + ((c + 1) & 1) * (64 * VSTR);
            const float* ks = Kb + (size_t)(c + 1) * CK * DDIM;
            const float* vs = Vb + (size_t)(c + 1) * CK * DDIM;
#pragma unroll
            for (int j = 0; j < 4; j++) {
                int i = t + THREADS * j, row = i >> 4, q = i & 15;
                cp16(kd + row * KSTR + q * 4, ks + (size_t)row * DDIM + q * 4);
                cp16(vd + row * VSTR + q * 4, vs + (size_t)row * DDIM + q * 4);
            }
            CP_COMMIT();
        }
        const float* Kc = Kbuf + (c & 1) * (64 * KSTR);
        const float* Vc = Vbuf + (c & 1) * (64 * VSTR);

#pragma unroll
        for (int s = 0; s < 2; s++) {
            // ---- scores for 4 n-tiles (16q x 32k) ----
            float sa[4][4];
#pragma unroll
            for (int n2 = 0; n2 < 4; n2++) {
                const int nt = s * 4 + n2;
                int2 mk0 = *(const int2*)(Mw + (size_t)grp * SDIM + c * CK + nt * 8 + tig * 2);
                int2 mk1 = *(const int2*)(Mw + (size_t)(grp + 8) * SDIM + c * CK + nt * 8 + tig * 2);
                float acc[4] = {0.f, 0.f, 0.f, 0.f};
                const float* kr = Kc + (nt * 8 + grp) * KSTR;
#pragma unroll
                for (int ks = 0; ks < 8; ks++) {
                    uint32_t b0 = f2tf(kr[ks * 8 + tig]);
                    uint32_t b1 = f2tf(kr[ks * 8 + tig + 4]);
                    mma_tf32(acc, aq[ks][0], aq[ks][1], aq[ks][2], aq[ks][3], b0, b1);
                }
                sa[n2][0] = mk0.x ? -1e9f : acc[0] * SCALE;
                sa[n2][1] = mk0.y ? -1e9f : acc[1] * SCALE;
                sa[n2][2] = mk1.x ? -1e9f : acc[2] * SCALE;
                sa[n2][3] = mk1.y ? -1e9f : acc[3] * SCALE;
            }

            // ---- online max update over this half-chunk ----
            float cm0 = fmaxf(fmaxf(sa[0][0], sa[0][1]), fmaxf(sa[1][0], sa[1][1]));
            cm0 = fmaxf(cm0, fmaxf(fmaxf(sa[2][0], sa[2][1]), fmaxf(sa[3][0], sa[3][1])));
            float cm1 = fmaxf(fmaxf(sa[0][2], sa[0][3]), fmaxf(sa[1][2], sa[1][3]));
            cm1 = fmaxf(cm1, fmaxf(fmaxf(sa[2][2], sa[2][3]), fmaxf(sa[3][2], sa[3][3])));
            cm0 = fmaxf(cm0, __shfl_xor_sync(0xffffffffu, cm0, 1));
            cm0 = fmaxf(cm0, __shfl_xor_sync(0xffffffffu, cm0, 2));
            cm1 = fmaxf(cm1, __shfl_xor_sync(0xffffffffu, cm1, 1));
            cm1 = fmaxf(cm1, __shfl_xor_sync(0xffffffffu, cm1, 2));
            float nm0 = fmaxf(m0, cm0), nm1 = fmaxf(m1, cm1);
            float f0 = __expf(m0 - nm0), f1 = __expf(m1 - nm1);
            m0 = nm0; m1 = nm1;
            sum0 *= f0; sum1 *= f1;
#pragma unroll
            for (int dn = 0; dn < 8; dn++) {
                cc[dn][0] *= f0; cc[dn][1] *= f0;
                cc[dn][2] *= f1; cc[dn][3] *= f1;
            }

            // ---- per n-tile: stage raw, exp, permute, context mma ----
#pragma unroll
            for (int n2 = 0; n2 < 4; n2++) {
                const int nt = s * 4 + n2;
                *(float2*)(stg + grp * STSTR + nt * 8 + tig * 2) =
                    make_float2(sa[n2][0], sa[n2][1]);
                *(float2*)(stg + (grp + 8) * STSTR + nt * 8 + tig * 2) =
                    make_float2(sa[n2][2], sa[n2][3]);

                float e00 = __expf(sa[n2][0] - m0), e01 = __expf(sa[n2][1] - m0);
                float e10 = __expf(sa[n2][2] - m1), e11 = __expf(sa[n2][3] - m1);
                sum0 += e00 + e01;
                sum1 += e10 + e11;

                float x0 = __shfl_sync(0xffffffffu, e00, src0);
                float x1 = __shfl_sync(0xffffffffu, e01, src0);
                float y0 = __shfl_sync(0xffffffffu, e00, src2);
                float y1 = __shfl_sync(0xffffffffu, e01, src2);
                float z0 = __shfl_sync(0xffffffffu, e10, src0);
                float z1 = __shfl_sync(0xffffffffu, e11, src0);
                float u0 = __shfl_sync(0xffffffffu, e10, src2);
                float u1 = __shfl_sync(0xffffffffu, e11, src2);
                uint32_t a0 = f2tf(odd ? x1 : x0);
                uint32_t a1 = f2tf(odd ? z1 : z0);
                uint32_t a2 = f2tf(odd ? y1 : y0);
                uint32_t a3 = f2tf(odd ? u1 : u0);

                const float* vr = Vc + (nt * 8 + tig) * VSTR;
#pragma unroll
                for (int dn = 0; dn < 8; dn++) {
                    uint32_t b0 = f2tf(vr[dn * 8 + grp]);
                    uint32_t b1 = f2tf(vr[4 * VSTR + dn * 8 + grp]);
                    mma_tf32(cc[dn], a0, a1, a2, a3, b0, b1);
                }
            }
        }

        // ---- stream raw score tile (16 x 64) to gmem, coalesced ----
        __syncwarp();
#pragma unroll
        for (int j = 0; j < 4; j++) {
            int idx = lane + 32 * j;       // 0..127
            int row = idx >> 3, c4 = idx & 7;   // 16 rows x 8 float4... (64 cols = 16 f4)
            // 16 rows x 16 float4 = 256; do 8 per lane via two sub-iterations
            float4 v0 = *(float4*)(stg + row * STSTR + c4 * 4);
            float4 v1 = *(float4*)(stg + row * STSTR + (c4 + 8) * 4);
            float* wr = Ww + (size_t)row * SDIM + c * CK;
            *(float4*)(wr + c4 * 4)       = v0;
            *(float4*)(wr + (c4 + 8) * 4) = v1;
        }
    }

    // ================= epilogue (warp-private rows: no cross-warp merge) ====
    sum0 += __shfl_xor_sync(0xffffffffu, sum0, 1);
    sum0 += __shfl_xor_sync(0xffffffffu, sum0, 2);
    sum1 += __shfl_xor_sync(0xffffffffu, sum1, 1);
    sum1 += __shfl_xor_sync(0xffffffffu, sum1, 2);
    const float ri0 = 1.0f / sum0, ri1 = 1.0f / sum1;
    if (tig == 0) {
        g_m [(size_t)bh * SDIM + qw + grp]      = m0;
        g_m [(size_t)bh * SDIM + qw + grp + 8]  = m1;
        g_ri[(size_t)bh * SDIM + qw + grp]      = ri0;
        g_ri[(size_t)bh * SDIM + qw + grp + 8]  = ri1;
    }
#pragma unroll
    for (int dn = 0; dn < 8; dn++) {
        *(float2*)(Cw + (size_t)grp * DDIM + dn * 8 + tig * 2) =
            make_float2(cc[dn][0] * ri0, cc[dn][1] * ri0);
        *(float2*)(Cw + (size_t)(grp + 8) * DDIM + dn * 8 + tig * 2) =
            make_float2(cc[dn][2] * ri1, cc[dn][3] * ri1);
    }
}

// ---- kernel 2: w = exp(s - m) * rinv, in place over the weights buffer ----
__global__ __launch_bounds__(128)
void attn_pass2(float* __restrict__ wout)
{
    const int row = blockIdx.x;                  // 0 .. BHN*SDIM-1
    const float m  = g_m[row];
    const float ri = g_ri[row];
    float4* p = (float4*)(wout + (size_t)row * SDIM);
#pragma unroll
    for (int j = 0; j < 4; j++) {
        int i4 = threadIdx.x + 128 * j;
        float4 s = p[i4];
        s.x = __expf(s.x - m) * ri;
        s.y = __expf(s.y - m) * ri;
        s.z = __expf(s.z - m) * ri;
        s.w = __expf(s.w - m) * ri;
        p[i4] = s;
    }
}

extern "C" void kernel_launch(void* const* d_in, const int* in_sizes, int n_in,
                              void* d_out, int out_size)
{
    const float* Q = (const float*)d_in[0];
    const float* K = (const float*)d_in[1];
    const float* V = (const float*)d_in[2];
    const int*   M = (const int*)d_in[3];

    float* ctx  = (float*)d_out;
    float* wout = (float*)d_out + (size_t)BHN * SDIM * DDIM;

    const size_t smem = (size_t)SMEM_FLOATS * sizeof(float);   // ~106 KB
    cudaFuncSetAttribute(attn_pass1,
                         cudaFuncAttributeMaxDynamicSharedMemorySize, (int)smem);

    dim3 grid1(SDIM / TQ, BHN);    // 16 x 32 = 512 CTAs
    attn_pass1<<<grid1, THREADS, smem>>>(Q, K, V, M, ctx, wout);
    attn_pass2<<<BHN * SDIM, 128>>>(wout);
}